// round 1
// baseline (speedup 1.0000x reference)
#include <cuda_runtime.h>

#define NQ 4
#define DIM 16
#define NPARAMS 36

// U stored transposed: g_Ur[j][k] = Re(U[k][j]), so the main kernel's
// j-outer accumulation loop reads contiguous 16-float rows (broadcast LDS).
__device__ float g_Ur[DIM][DIM];
__device__ float g_Ui[DIM][DIM];

// ---------------------------------------------------------------------------
// Build the 16x16 variational unitary from params. One thread per COLUMN of U
// (columns evolve independently under left-multiplication by gates), so no
// synchronization is needed. Everything is fully unrolled: the CNOT layers
// become compile-time register renames.
// ---------------------------------------------------------------------------
__global__ void build_U_kernel(const float* __restrict__ params) {
    const int c = threadIdx.x;
    if (c >= DIM) return;

    float P[NPARAMS];
#pragma unroll
    for (int i = 0; i < NPARAMS; i++) P[i] = params[i];

    float ur[DIM], ui[DIM];
#pragma unroll
    for (int j = 0; j < DIM; j++) { ur[j] = (j == c) ? 1.0f : 0.0f; ui[j] = 0.0f; }

    int off = 0;
#pragma unroll
    for (int layer = 0; layer < 3; layer++) {
#pragma unroll
        for (int w = 0; w < NQ; w++) {
            const int bit = 1 << (NQ - 1 - w);  // wire 0 = MSB (big-endian)

            // RY(P[off])
            {
                float s, co;
                __sincosf(0.5f * P[off], &s, &co); off++;
#pragma unroll
                for (int r = 0; r < DIM; r++) {
                    if (r & bit) continue;
                    const int r1 = r | bit;
                    float v0r = ur[r], v0i = ui[r], v1r = ur[r1], v1i = ui[r1];
                    ur[r]  = co * v0r - s * v1r;
                    ui[r]  = co * v0i - s * v1i;
                    ur[r1] = s * v0r + co * v1r;
                    ui[r1] = s * v0i + co * v1i;
                }
            }
            // RZ(P[off]): diag(e^{-it/2}, e^{+it/2})
            {
                float s, co;
                __sincosf(0.5f * P[off], &s, &co); off++;
#pragma unroll
                for (int r = 0; r < DIM; r++) {
                    float vr = ur[r], vi = ui[r];
                    if (r & bit) { ur[r] = co * vr - s * vi; ui[r] = co * vi + s * vr; }
                    else         { ur[r] = co * vr + s * vi; ui[r] = co * vi - s * vr; }
                }
            }
            // RY(P[off])
            {
                float s, co;
                __sincosf(0.5f * P[off], &s, &co); off++;
#pragma unroll
                for (int r = 0; r < DIM; r++) {
                    if (r & bit) continue;
                    const int r1 = r | bit;
                    float v0r = ur[r], v0i = ui[r], v1r = ur[r1], v1i = ui[r1];
                    ur[r]  = co * v0r - s * v1r;
                    ui[r]  = co * v0i - s * v1i;
                    ur[r1] = s * v0r + co * v1r;
                    ui[r1] = s * v0i + co * v1i;
                }
            }
        }
        // Entangling layer: CNOT(0,1), CNOT(1,2), CNOT(2,3), CNOT(3,0).
        // Each is a pure row swap (compile-time unrolled -> free renames).
#pragma unroll
        for (int g = 0; g < NQ; g++) {
            const int ctrl = g, tgt = (g + 1) & 3;
            const int cb = 1 << (NQ - 1 - ctrl);
            const int tb = 1 << (NQ - 1 - tgt);
#pragma unroll
            for (int r = 0; r < DIM; r++) {
                if ((r & cb) && !(r & tb)) {
                    const int r1 = r | tb;
                    float t;
                    t = ur[r]; ur[r] = ur[r1]; ur[r1] = t;
                    t = ui[r]; ui[r] = ui[r1]; ui[r1] = t;
                }
            }
        }
    }

    // Thread c owns column c of U => write transposed row c of G.
#pragma unroll
    for (int k = 0; k < DIM; k++) {
        g_Ur[c][k] = ur[k];
        g_Ui[c][k] = ui[k];
    }
}

// ---------------------------------------------------------------------------
// Main kernel: one thread per 2x2 patch.
//   psi0 (real, 16) = kron of 4 RY-encoded qubits
//   y = U psi0  (two real 16x16 matvecs, 512 FFMA)
//   expvals = signed sums of |y|^2
// ---------------------------------------------------------------------------
__global__ void __launch_bounds__(256) quanv_kernel(
    const float* __restrict__ x, float* __restrict__ out, int npatch)
{
    __shared__ float sUr[DIM][DIM];
    __shared__ float sUi[DIM][DIM];

    const int tid = threadIdx.x;
    // 2*256 floats, 256 threads -> one each
    ((float*)sUr)[tid] = ((const float*)g_Ur)[tid];
    ((float*)sUi)[tid] = ((const float*)g_Ui)[tid];
    __syncthreads();

    const int p = blockIdx.x * 256 + tid;
    if (p >= npatch) return;

    // p -> (batch b, patch row r, patch col cc)
    const int b  = p / 196;
    const int q  = p - b * 196;
    const int r  = q / 14;
    const int cc = q - r * 14;

    const float* base = x + b * 784 + r * 56 + cc * 2;
    const float2 v01 = *(const float2*)(base);        // row 2r  : cols 2c, 2c+1
    const float2 v23 = *(const float2*)(base + 28);   // row 2r+1: cols 2c, 2c+1

    // RY(v*pi)|0> = [cos(v*pi/2), sin(v*pi/2)]
    const float HPI = 1.5707963267948966f;
    float a0, b0, a1, b1, a2, b2, a3, b3;
    __sincosf(v01.x * HPI, &b0, &a0);
    __sincosf(v01.y * HPI, &b1, &a1);
    __sincosf(v23.x * HPI, &b2, &a2);
    __sincosf(v23.y * HPI, &b3, &a3);

    float p01[4] = { a0 * a1, a0 * b1, b0 * a1, b0 * b1 };
    float p23[4] = { a2 * a3, a2 * b3, b2 * a3, b2 * b3 };

    float yr[DIM], yi[DIM];
#pragma unroll
    for (int k = 0; k < DIM; k++) { yr[k] = 0.0f; yi[k] = 0.0f; }

#pragma unroll
    for (int j = 0; j < DIM; j++) {
        const float pj = p01[j >> 2] * p23[j & 3];
#pragma unroll
        for (int k = 0; k < DIM; k++) {
            yr[k] = fmaf(sUr[j][k], pj, yr[k]);
            yi[k] = fmaf(sUi[j][k], pj, yi[k]);
        }
    }

    float e0 = 0.0f, e1 = 0.0f, e2 = 0.0f, e3 = 0.0f;
#pragma unroll
    for (int k = 0; k < DIM; k++) {
        const float pr = yr[k] * yr[k] + yi[k] * yi[k];
        e0 += (k & 8) ? -pr : pr;
        e1 += (k & 4) ? -pr : pr;
        e2 += (k & 2) ? -pr : pr;
        e3 += (k & 1) ? -pr : pr;
    }

    float4 o; o.x = e0; o.y = e1; o.z = e2; o.w = e3;
    *(float4*)(out + 4 * p) = o;
}

extern "C" void kernel_launch(void* const* d_in, const int* in_sizes, int n_in,
                              void* d_out, int out_size) {
    const float* x      = (const float*)d_in[0];
    const float* params = (const float*)d_in[1];
    float* out = (float*)d_out;

    const int bsz    = in_sizes[0] / 784;
    const int npatch = bsz * 196;

    build_U_kernel<<<1, 32>>>(params);

    const int threads = 256;
    const int blocks  = (npatch + threads - 1) / threads;
    quanv_kernel<<<blocks, threads>>>(x, out, npatch);
}

// round 2
// speedup vs baseline: 1.2002x; 1.2002x over previous
#include <cuda_runtime.h>

#define NQ 4
#define DIM 16
#define NPARAMS 36

typedef unsigned long long u64;

// U stored transposed: g_Ur[j][k] = Re(U[k][j]) so row j is contiguous.
__device__ float g_Ur[DIM][DIM];
__device__ float g_Ui[DIM][DIM];

// ---------------- packed f32x2 helpers (SASS FFMA2 path) ----------------
__device__ __forceinline__ u64 fma2(u64 a, u64 b, u64 c) {
    u64 d;
    asm("fma.rn.f32x2 %0, %1, %2, %3;" : "=l"(d) : "l"(a), "l"(b), "l"(c));
    return d;
}
__device__ __forceinline__ u64 mul2(u64 a, u64 b) {
    u64 d;
    asm("mul.rn.f32x2 %0, %1, %2;" : "=l"(d) : "l"(a), "l"(b));
    return d;
}
__device__ __forceinline__ u64 pack2(float lo, float hi) {
    u64 d;
    asm("mov.b64 %0, {%1, %2};" : "=l"(d) : "f"(lo), "f"(hi));
    return d;
}
__device__ __forceinline__ void unpack2(u64 v, float& lo, float& hi) {
    asm("mov.b64 {%0, %1}, %2;" : "=f"(lo), "=f"(hi) : "l"(v));
}

// ---------------------------------------------------------------------------
// Build the 16x16 variational unitary from params. One thread per COLUMN of U.
// ---------------------------------------------------------------------------
__global__ void build_U_kernel(const float* __restrict__ params) {
    const int c = threadIdx.x;
    if (c >= DIM) return;

    float P[NPARAMS];
#pragma unroll
    for (int i = 0; i < NPARAMS; i++) P[i] = params[i];

    float ur[DIM], ui[DIM];
#pragma unroll
    for (int j = 0; j < DIM; j++) { ur[j] = (j == c) ? 1.0f : 0.0f; ui[j] = 0.0f; }

    int off = 0;
#pragma unroll
    for (int layer = 0; layer < 3; layer++) {
#pragma unroll
        for (int w = 0; w < NQ; w++) {
            const int bit = 1 << (NQ - 1 - w);  // wire 0 = MSB (big-endian)
            // RY
            {
                float s, co;
                __sincosf(0.5f * P[off], &s, &co); off++;
#pragma unroll
                for (int r = 0; r < DIM; r++) {
                    if (r & bit) continue;
                    const int r1 = r | bit;
                    float v0r = ur[r], v0i = ui[r], v1r = ur[r1], v1i = ui[r1];
                    ur[r]  = co * v0r - s * v1r;
                    ui[r]  = co * v0i - s * v1i;
                    ur[r1] = s * v0r + co * v1r;
                    ui[r1] = s * v0i + co * v1i;
                }
            }
            // RZ: diag(e^{-it/2}, e^{+it/2})
            {
                float s, co;
                __sincosf(0.5f * P[off], &s, &co); off++;
#pragma unroll
                for (int r = 0; r < DIM; r++) {
                    float vr = ur[r], vi = ui[r];
                    if (r & bit) { ur[r] = co * vr - s * vi; ui[r] = co * vi + s * vr; }
                    else         { ur[r] = co * vr + s * vi; ui[r] = co * vi - s * vr; }
                }
            }
            // RY
            {
                float s, co;
                __sincosf(0.5f * P[off], &s, &co); off++;
#pragma unroll
                for (int r = 0; r < DIM; r++) {
                    if (r & bit) continue;
                    const int r1 = r | bit;
                    float v0r = ur[r], v0i = ui[r], v1r = ur[r1], v1i = ui[r1];
                    ur[r]  = co * v0r - s * v1r;
                    ui[r]  = co * v0i - s * v1i;
                    ur[r1] = s * v0r + co * v1r;
                    ui[r1] = s * v0i + co * v1i;
                }
            }
        }
        // Entangling layer: CNOT(0,1), CNOT(1,2), CNOT(2,3), CNOT(3,0) = row swaps
#pragma unroll
        for (int g = 0; g < NQ; g++) {
            const int ctrl = g, tgt = (g + 1) & 3;
            const int cb = 1 << (NQ - 1 - ctrl);
            const int tb = 1 << (NQ - 1 - tgt);
#pragma unroll
            for (int r = 0; r < DIM; r++) {
                if ((r & cb) && !(r & tb)) {
                    const int r1 = r | tb;
                    float t;
                    t = ur[r]; ur[r] = ur[r1]; ur[r1] = t;
                    t = ui[r]; ui[r] = ui[r1]; ui[r1] = t;
                }
            }
        }
    }

#pragma unroll
    for (int k = 0; k < DIM; k++) {
        g_Ur[c][k] = ur[k];
        g_Ui[c][k] = ui[k];
    }
}

// ---------------------------------------------------------------------------
// Main kernel: 2 patches per thread, packed f32x2 matvec.
// ---------------------------------------------------------------------------
__global__ void __launch_bounds__(256) quanv_kernel(
    const float* __restrict__ x, float* __restrict__ out, int npatch)
{
    __shared__ float sUr[DIM][DIM];
    __shared__ float sUi[DIM][DIM];

    const int tid = threadIdx.x;
    ((float*)sUr)[tid] = ((const float*)g_Ur)[tid];
    ((float*)sUi)[tid] = ((const float*)g_Ui)[tid];
    __syncthreads();

    const int g  = blockIdx.x * 256 + tid;
    const int p0 = 2 * g;
    if (p0 >= npatch) return;

    const float HPI = 1.5707963267948966f;

    // Per-patch duplicated packed factors: p01d[a] = {p01[a], p01[a]}
    u64 p01d[2][4], p23d[2][4];
#pragma unroll
    for (int pp = 0; pp < 2; pp++) {
        const int p  = p0 + pp;
        const int b  = p / 196;
        const int q  = p - b * 196;
        const int r  = q / 14;
        const int cc = q - r * 14;

        const float* base = x + b * 784 + r * 56 + cc * 2;
        const float2 v01 = *(const float2*)(base);
        const float2 v23 = *(const float2*)(base + 28);

        float a0, b0, a1, b1, a2, b2, a3, b3;
        __sincosf(v01.x * HPI, &b0, &a0);
        __sincosf(v01.y * HPI, &b1, &a1);
        __sincosf(v23.x * HPI, &b2, &a2);
        __sincosf(v23.y * HPI, &b3, &a3);

        const float q01[4] = { a0 * a1, a0 * b1, b0 * a1, b0 * b1 };
        const float q23[4] = { a2 * a3, a2 * b3, b2 * a3, b2 * b3 };
#pragma unroll
        for (int a = 0; a < 4; a++) {
            p01d[pp][a] = pack2(q01[a], q01[a]);
            p23d[pp][a] = pack2(q23[a], q23[a]);
        }
    }

    // Packed accumulators: 8 pairs (k=2t, 2t+1) for Re and Im, per patch.
    u64 accR[2][8], accI[2][8];
#pragma unroll
    for (int pp = 0; pp < 2; pp++)
#pragma unroll
        for (int t = 0; t < 8; t++) { accR[pp][t] = 0ULL; accI[pp][t] = 0ULL; }

#pragma unroll
    for (int j = 0; j < DIM; j++) {
        // Load row j of Re/Im U once (8+8 packed pairs), reuse for both patches.
        const u64* rowR = (const u64*)sUr[j];
        const u64* rowI = (const u64*)sUi[j];
        u64 uR[8], uI[8];
#pragma unroll
        for (int t = 0; t < 8; t++) { uR[t] = rowR[t]; uI[t] = rowI[t]; }

#pragma unroll
        for (int pp = 0; pp < 2; pp++) {
            const u64 pj = mul2(p01d[pp][j >> 2], p23d[pp][j & 3]);
#pragma unroll
            for (int t = 0; t < 8; t++) accR[pp][t] = fma2(uR[t], pj, accR[pp][t]);
#pragma unroll
            for (int t = 0; t < 8; t++) accI[pp][t] = fma2(uI[t], pj, accI[pp][t]);
        }
    }

    // Epilogue: probs = |y|^2 (packed), then signed reductions.
#pragma unroll
    for (int pp = 0; pp < 2; pp++) {
        float e0 = 0.0f, e1 = 0.0f, e2 = 0.0f, e3 = 0.0f;
#pragma unroll
        for (int t = 0; t < 8; t++) {
            const u64 pr2 = fma2(accI[pp][t], accI[pp][t],
                                 mul2(accR[pp][t], accR[pp][t]));
            float lo, hi;
            unpack2(pr2, lo, hi);
            const float s = lo + hi;   // k = 2t, 2t+1 share bits 1..3
            const float d = lo - hi;   // bit0 sign: +lo - hi
            e3 += d;
            e2 += (t & 1) ? -s : s;    // bit1 of k = t&1
            e1 += (t & 2) ? -s : s;    // bit2 of k
            e0 += (t & 4) ? -s : s;    // bit3 of k
        }
        float4 o; o.x = e0; o.y = e1; o.z = e2; o.w = e3;
        *(float4*)(out + 4 * (p0 + pp)) = o;
    }
}

extern "C" void kernel_launch(void* const* d_in, const int* in_sizes, int n_in,
                              void* d_out, int out_size) {
    const float* x      = (const float*)d_in[0];
    const float* params = (const float*)d_in[1];
    float* out = (float*)d_out;

    const int bsz     = in_sizes[0] / 784;
    const int npatch  = bsz * 196;
    const int nthread = (npatch + 1) / 2;

    build_U_kernel<<<1, 32>>>(params);

    const int threads = 256;
    const int blocks  = (nthread + threads - 1) / threads;
    quanv_kernel<<<blocks, threads>>>(x, out, npatch);
}

// round 3
// speedup vs baseline: 1.5151x; 1.2624x over previous
#include <cuda_runtime.h>
#include <cuda_bf16.h>

#define NQ 4
#define DIM 16
#define NPARAMS 36

typedef unsigned int u32;

// bf16-split of the 16x16 unitary, row-major [k][j]  (k = output index, j = psi index)
__device__ __nv_bfloat16 g_Uh_r[DIM][DIM];
__device__ __nv_bfloat16 g_Ul_r[DIM][DIM];
__device__ __nv_bfloat16 g_Uh_i[DIM][DIM];
__device__ __nv_bfloat16 g_Ul_i[DIM][DIM];

// ---------------------------------------------------------------------------
// Build U(params). One thread per COLUMN c of U (c = psi index j).
// ---------------------------------------------------------------------------
__global__ void build_U_kernel(const float* __restrict__ params) {
    const int c = threadIdx.x;
    if (c >= DIM) return;

    float P[NPARAMS];
#pragma unroll
    for (int i = 0; i < NPARAMS; i++) P[i] = params[i];

    float ur[DIM], ui[DIM];
#pragma unroll
    for (int j = 0; j < DIM; j++) { ur[j] = (j == c) ? 1.0f : 0.0f; ui[j] = 0.0f; }

    int off = 0;
#pragma unroll
    for (int layer = 0; layer < 3; layer++) {
#pragma unroll
        for (int w = 0; w < NQ; w++) {
            const int bit = 1 << (NQ - 1 - w);
            // RY
            {
                float s, co; __sincosf(0.5f * P[off], &s, &co); off++;
#pragma unroll
                for (int r = 0; r < DIM; r++) {
                    if (r & bit) continue;
                    const int r1 = r | bit;
                    float v0r = ur[r], v0i = ui[r], v1r = ur[r1], v1i = ui[r1];
                    ur[r]  = co * v0r - s * v1r;   ui[r]  = co * v0i - s * v1i;
                    ur[r1] = s * v0r + co * v1r;   ui[r1] = s * v0i + co * v1i;
                }
            }
            // RZ
            {
                float s, co; __sincosf(0.5f * P[off], &s, &co); off++;
#pragma unroll
                for (int r = 0; r < DIM; r++) {
                    float vr = ur[r], vi = ui[r];
                    if (r & bit) { ur[r] = co * vr - s * vi; ui[r] = co * vi + s * vr; }
                    else         { ur[r] = co * vr + s * vi; ui[r] = co * vi - s * vr; }
                }
            }
            // RY
            {
                float s, co; __sincosf(0.5f * P[off], &s, &co); off++;
#pragma unroll
                for (int r = 0; r < DIM; r++) {
                    if (r & bit) continue;
                    const int r1 = r | bit;
                    float v0r = ur[r], v0i = ui[r], v1r = ur[r1], v1i = ui[r1];
                    ur[r]  = co * v0r - s * v1r;   ui[r]  = co * v0i - s * v1i;
                    ur[r1] = s * v0r + co * v1r;   ui[r1] = s * v0i + co * v1i;
                }
            }
        }
        // CNOT ring = row swaps
#pragma unroll
        for (int g = 0; g < NQ; g++) {
            const int cb = 1 << (NQ - 1 - g);
            const int tb = 1 << (NQ - 1 - ((g + 1) & 3));
#pragma unroll
            for (int r = 0; r < DIM; r++) {
                if ((r & cb) && !(r & tb)) {
                    const int r1 = r | tb;
                    float t;
                    t = ur[r]; ur[r] = ur[r1]; ur[r1] = t;
                    t = ui[r]; ui[r] = ui[r1]; ui[r1] = t;
                }
            }
        }
    }

#pragma unroll
    for (int k = 0; k < DIM; k++) {
        __nv_bfloat16 h;
        h = __float2bfloat16(ur[k]);
        g_Uh_r[k][c] = h;
        g_Ul_r[k][c] = __float2bfloat16(ur[k] - __bfloat162float(h));
        h = __float2bfloat16(ui[k]);
        g_Uh_i[k][c] = h;
        g_Ul_i[k][c] = __float2bfloat16(ui[k] - __bfloat162float(h));
    }
}

// ---------------- helpers ----------------
__device__ __forceinline__ u32 pack_bf16x2(float lo, float hi) {
    u32 d;
    asm("cvt.rn.bf16x2.f32 %0, %1, %2;" : "=r"(d) : "f"(hi), "f"(lo));
    return d;
}
__device__ __forceinline__ void mma_bf16(float c[4], const u32 a[4], const u32 b[2]) {
    asm volatile(
        "mma.sync.aligned.m16n8k16.row.col.f32.bf16.bf16.f32 "
        "{%0,%1,%2,%3}, {%4,%5,%6,%7}, {%8,%9}, {%0,%1,%2,%3};"
        : "+f"(c[0]), "+f"(c[1]), "+f"(c[2]), "+f"(c[3])
        : "r"(a[0]), "r"(a[1]), "r"(a[2]), "r"(a[3]), "r"(b[0]), "r"(b[1]));
}

// ---------------------------------------------------------------------------
// Main kernel: 1 patch/thread; warp does 32 patches = 2 m16 MMA tiles.
// y = U psi0 via bf16-split mma: Uh*Ph + Uh*Pl + Ul*Ph  (fp32 accum).
// ---------------------------------------------------------------------------
__global__ void __launch_bounds__(256) quanv_kernel(
    const float* __restrict__ x, float* __restrict__ out, int npatch)
{
    // staging: 8 warps x 32 patch slots x 80B (Ph[16 bf16] @0, Pl @32, pad)
    __shared__ __align__(16) unsigned char stage[8 * 32 * 80];

    const int tid  = threadIdx.x;
    const int lane = tid & 31;
    const int wrp  = tid >> 5;
    const int g    = lane >> 2;   // mma groupID
    const int t    = lane & 3;    // mma threadID-in-group

    const int warpbase = blockIdx.x * 256 + wrp * 32;
    const int p  = warpbase + lane;
    const int pc = (p < npatch) ? p : (npatch - 1);

    // ---- patch -> pixels ----
    const int b  = pc / 196;
    const int q  = pc - b * 196;
    const int r  = q / 14;
    const int cc = q - r * 14;
    const float* base = x + b * 784 + r * 56 + cc * 2;
    const float2 v01 = *(const float2*)(base);
    const float2 v23 = *(const float2*)(base + 28);

    // ---- psi0 (real, 16) ----
    const float HPI = 1.5707963267948966f;
    float a0, b0, a1, b1, a2, b2, a3, b3;
    __sincosf(v01.x * HPI, &b0, &a0);
    __sincosf(v01.y * HPI, &b1, &a1);
    __sincosf(v23.x * HPI, &b2, &a2);
    __sincosf(v23.y * HPI, &b3, &a3);
    const float q01[4] = { a0 * a1, a0 * b1, b0 * a1, b0 * b1 };
    const float q23[4] = { a2 * a3, a2 * b3, b2 * a3, b2 * b3 };

    float v[DIM];
#pragma unroll
    for (int a = 0; a < 4; a++)
#pragma unroll
        for (int c = 0; c < 4; c++) v[4 * a + c] = q01[a] * q23[c];

    // ---- bf16 split + pack: Ph = bf16(v), Pl = bf16(v - Ph) ----
    u32 ph[8], pl[8];
#pragma unroll
    for (int m = 0; m < 8; m++) {
        const float lo = v[2 * m], hi = v[2 * m + 1];
        const u32 p2 = pack_bf16x2(lo, hi);
        const float flo = __uint_as_float(p2 << 16);
        const float fhi = __uint_as_float(p2 & 0xffff0000u);
        ph[m] = p2;
        pl[m] = pack_bf16x2(lo - flo, hi - fhi);
    }

    // ---- stage to SMEM ----
    unsigned char* const ws = stage + wrp * (32 * 80);
    {
        uint4* slot = (uint4*)(ws + lane * 80);
        slot[0] = make_uint4(ph[0], ph[1], ph[2], ph[3]);
        slot[1] = make_uint4(ph[4], ph[5], ph[6], ph[7]);
        slot[2] = make_uint4(pl[0], pl[1], pl[2], pl[3]);
        slot[3] = make_uint4(pl[4], pl[5], pl[6], pl[7]);
    }

    // ---- B fragments (U, warp-resident for all patches) ----
    // b0 = U[kk][2t,2t+1], b1 = U[kk][2t+8,2t+9], kk = 8*nt + g
    u32 Bhr[2][2], Bhi[2][2], Blr[2][2], Bli[2][2];
#pragma unroll
    for (int nt = 0; nt < 2; nt++) {
        const int kk = 8 * nt + g;
        Bhr[nt][0] = *(const u32*)&g_Uh_r[kk][2 * t];
        Bhr[nt][1] = *(const u32*)&g_Uh_r[kk][2 * t + 8];
        Bhi[nt][0] = *(const u32*)&g_Uh_i[kk][2 * t];
        Bhi[nt][1] = *(const u32*)&g_Uh_i[kk][2 * t + 8];
        Blr[nt][0] = *(const u32*)&g_Ul_r[kk][2 * t];
        Blr[nt][1] = *(const u32*)&g_Ul_r[kk][2 * t + 8];
        Bli[nt][0] = *(const u32*)&g_Ul_i[kk][2 * t];
        Bli[nt][1] = *(const u32*)&g_Ul_i[kk][2 * t + 8];
    }

    __syncwarp();

    // ---- MMAs: 2 tiles x 2 n-halves x (Re,Im) accumulators ----
    float Cr[2][2][4], Ci[2][2][4];
#pragma unroll
    for (int T = 0; T < 2; T++)
#pragma unroll
        for (int nt = 0; nt < 2; nt++)
#pragma unroll
            for (int k = 0; k < 4; k++) { Cr[T][nt][k] = 0.0f; Ci[T][nt][k] = 0.0f; }

#pragma unroll
    for (int T = 0; T < 2; T++) {
        const unsigned char* s0 = ws + (T * 16 + g) * 80;       // row g
        const unsigned char* s1 = ws + (T * 16 + g + 8) * 80;   // row g+8
        u32 Aph[4], Apl[4];
        Aph[0] = *(const u32*)(s0 + 4 * t);
        Aph[1] = *(const u32*)(s1 + 4 * t);
        Aph[2] = *(const u32*)(s0 + 16 + 4 * t);
        Aph[3] = *(const u32*)(s1 + 16 + 4 * t);
        Apl[0] = *(const u32*)(s0 + 32 + 4 * t);
        Apl[1] = *(const u32*)(s1 + 32 + 4 * t);
        Apl[2] = *(const u32*)(s0 + 48 + 4 * t);
        Apl[3] = *(const u32*)(s1 + 48 + 4 * t);

#pragma unroll
        for (int nt = 0; nt < 2; nt++) {
            mma_bf16(Cr[T][nt], Aph, Bhr[nt]);   // Uh * Ph
            mma_bf16(Cr[T][nt], Apl, Bhr[nt]);   // Uh * Pl
            mma_bf16(Cr[T][nt], Aph, Blr[nt]);   // Ul * Ph
            mma_bf16(Ci[T][nt], Aph, Bhi[nt]);
            mma_bf16(Ci[T][nt], Apl, Bhi[nt]);
            mma_bf16(Ci[T][nt], Aph, Bli[nt]);
        }
    }

    // ---- epilogue: |y|^2, signed sums over k, quad reduction ----
    // lane's C holds k = {8*nt + 2t, 8*nt + 2t + 1}; bit3=nt, bit2=(t&2), bit1=(t&1), bit0=c-parity
    float o0 = 0.f, o1 = 0.f, o2 = 0.f, o3 = 0.f;
#pragma unroll
    for (int cse = 0; cse < 4; cse++) {
        const int T   = cse >> 1;
        const int hi8 = cse & 1;  // 0 -> row g, 1 -> row g+8
        const float r0 = Cr[T][0][hi8 * 2 + 0], i0 = Ci[T][0][hi8 * 2 + 0];
        const float r1 = Cr[T][0][hi8 * 2 + 1], i1 = Ci[T][0][hi8 * 2 + 1];
        const float r2 = Cr[T][1][hi8 * 2 + 0], i2 = Ci[T][1][hi8 * 2 + 0];
        const float r3 = Cr[T][1][hi8 * 2 + 1], i3 = Ci[T][1][hi8 * 2 + 1];

        const float A = fmaf(r0, r0, i0 * i0);   // k = 2t
        const float B = fmaf(r1, r1, i1 * i1);   // k = 2t+1
        const float C = fmaf(r2, r2, i2 * i2);   // k = 2t+8
        const float D = fmaf(r3, r3, i3 * i3);   // k = 2t+9

        const float s01 = A + B, s23 = C + D;
        float pe0 = s01 - s23;                    // bit3 sign
        float pe3 = (A - B) + (C - D);            // bit0 sign
        const float sAll = s01 + s23;
        float pe1 = (t & 2) ? -sAll : sAll;       // bit2 sign (lane-dependent)
        float pe2 = (t & 1) ? -sAll : sAll;       // bit1 sign (lane-dependent)

        // reduce across the 4 lanes of the quad
        pe0 += __shfl_xor_sync(0xffffffffu, pe0, 1);
        pe1 += __shfl_xor_sync(0xffffffffu, pe1, 1);
        pe2 += __shfl_xor_sync(0xffffffffu, pe2, 1);
        pe3 += __shfl_xor_sync(0xffffffffu, pe3, 1);
        pe0 += __shfl_xor_sync(0xffffffffu, pe0, 2);
        pe1 += __shfl_xor_sync(0xffffffffu, pe1, 2);
        pe2 += __shfl_xor_sync(0xffffffffu, pe2, 2);
        pe3 += __shfl_xor_sync(0xffffffffu, pe3, 2);

        if (cse == t) { o0 = pe0; o1 = pe1; o2 = pe2; o3 = pe3; }
    }

    // lane t stores case t: patch = warpbase + (t>>1)*16 + g + (t&1)*8
    const int pstore = warpbase + (t >> 1) * 16 + g + (t & 1) * 8;
    if (pstore < npatch) {
        float4 o; o.x = o0; o.y = o1; o.z = o2; o.w = o3;
        *(float4*)(out + 4 * pstore) = o;
    }
}

extern "C" void kernel_launch(void* const* d_in, const int* in_sizes, int n_in,
                              void* d_out, int out_size) {
    const float* x      = (const float*)d_in[0];
    const float* params = (const float*)d_in[1];
    float* out = (float*)d_out;

    const int bsz    = in_sizes[0] / 784;
    const int npatch = bsz * 196;

    build_U_kernel<<<1, 32>>>(params);

    const int threads = 256;
    const int blocks  = (npatch + threads - 1) / threads;
    quanv_kernel<<<blocks, threads>>>(x, out, npatch);
}

// round 4
// speedup vs baseline: 1.5319x; 1.0111x over previous
#include <cuda_runtime.h>
#include <cuda_bf16.h>

#define NQ 4
#define DIM 16
#define NPARAMS 36

typedef unsigned int u32;

// bf16-split of the 16x16 unitary, row-major [k][j]  (k = output index, j = psi index)
__device__ __nv_bfloat16 g_Uh_r[DIM][DIM];
__device__ __nv_bfloat16 g_Ul_r[DIM][DIM];
__device__ __nv_bfloat16 g_Uh_i[DIM][DIM];
__device__ __nv_bfloat16 g_Ul_i[DIM][DIM];

// Per-lane pre-packed B fragments: [lane][16] u32 =
//  {hr(nt0,b0),hr(nt0,b1),hr(nt1,b0),hr(nt1,b1),  hi...,  lr...,  li...}
__device__ u32 g_Bfrag[32][16];

// ---------------------------------------------------------------------------
// Build U(params): threads 0..15 each own one COLUMN of U; then all 32 lanes
// repack into mma B-fragment order.
// ---------------------------------------------------------------------------
__global__ void build_U_kernel(const float* __restrict__ params) {
    const int c = threadIdx.x;

    if (c < DIM) {
        float P[NPARAMS];
#pragma unroll
        for (int i = 0; i < NPARAMS; i++) P[i] = params[i];

        float ur[DIM], ui[DIM];
#pragma unroll
        for (int j = 0; j < DIM; j++) { ur[j] = (j == c) ? 1.0f : 0.0f; ui[j] = 0.0f; }

        int off = 0;
#pragma unroll
        for (int layer = 0; layer < 3; layer++) {
#pragma unroll
            for (int w = 0; w < NQ; w++) {
                const int bit = 1 << (NQ - 1 - w);
                // RY
                {
                    float s, co; __sincosf(0.5f * P[off], &s, &co); off++;
#pragma unroll
                    for (int r = 0; r < DIM; r++) {
                        if (r & bit) continue;
                        const int r1 = r | bit;
                        float v0r = ur[r], v0i = ui[r], v1r = ur[r1], v1i = ui[r1];
                        ur[r]  = co * v0r - s * v1r;   ui[r]  = co * v0i - s * v1i;
                        ur[r1] = s * v0r + co * v1r;   ui[r1] = s * v0i + co * v1i;
                    }
                }
                // RZ
                {
                    float s, co; __sincosf(0.5f * P[off], &s, &co); off++;
#pragma unroll
                    for (int r = 0; r < DIM; r++) {
                        float vr = ur[r], vi = ui[r];
                        if (r & bit) { ur[r] = co * vr - s * vi; ui[r] = co * vi + s * vr; }
                        else         { ur[r] = co * vr + s * vi; ui[r] = co * vi - s * vr; }
                    }
                }
                // RY
                {
                    float s, co; __sincosf(0.5f * P[off], &s, &co); off++;
#pragma unroll
                    for (int r = 0; r < DIM; r++) {
                        if (r & bit) continue;
                        const int r1 = r | bit;
                        float v0r = ur[r], v0i = ui[r], v1r = ur[r1], v1i = ui[r1];
                        ur[r]  = co * v0r - s * v1r;   ui[r]  = co * v0i - s * v1i;
                        ur[r1] = s * v0r + co * v1r;   ui[r1] = s * v0i + co * v1i;
                    }
                }
            }
            // CNOT ring = row swaps
#pragma unroll
            for (int g = 0; g < NQ; g++) {
                const int cb = 1 << (NQ - 1 - g);
                const int tb = 1 << (NQ - 1 - ((g + 1) & 3));
#pragma unroll
                for (int r = 0; r < DIM; r++) {
                    if ((r & cb) && !(r & tb)) {
                        const int r1 = r | tb;
                        float t;
                        t = ur[r]; ur[r] = ur[r1]; ur[r1] = t;
                        t = ui[r]; ui[r] = ui[r1]; ui[r1] = t;
                    }
                }
            }
        }

#pragma unroll
        for (int k = 0; k < DIM; k++) {
            __nv_bfloat16 h;
            h = __float2bfloat16(ur[k]);
            g_Uh_r[k][c] = h;
            g_Ul_r[k][c] = __float2bfloat16(ur[k] - __bfloat162float(h));
            h = __float2bfloat16(ui[k]);
            g_Uh_i[k][c] = h;
            g_Ul_i[k][c] = __float2bfloat16(ui[k] - __bfloat162float(h));
        }
    }

    __syncthreads();  // global writes by this block visible to this block

    // Phase 2: pack per-lane B fragments (lane = g*4 + t)
    {
        const int lane = threadIdx.x;
        const int g = lane >> 2, t = lane & 3;
        u32 frag[16];
#pragma unroll
        for (int nt = 0; nt < 2; nt++) {
            const int kk = 8 * nt + g;
            frag[0  + 2 * nt] = *(const u32*)&g_Uh_r[kk][2 * t];
            frag[1  + 2 * nt] = *(const u32*)&g_Uh_r[kk][2 * t + 8];
            frag[4  + 2 * nt] = *(const u32*)&g_Uh_i[kk][2 * t];
            frag[5  + 2 * nt] = *(const u32*)&g_Uh_i[kk][2 * t + 8];
            frag[8  + 2 * nt] = *(const u32*)&g_Ul_r[kk][2 * t];
            frag[9  + 2 * nt] = *(const u32*)&g_Ul_r[kk][2 * t + 8];
            frag[12 + 2 * nt] = *(const u32*)&g_Ul_i[kk][2 * t];
            frag[13 + 2 * nt] = *(const u32*)&g_Ul_i[kk][2 * t + 8];
        }
        uint4* dst = (uint4*)g_Bfrag[lane];
#pragma unroll
        for (int v = 0; v < 4; v++)
            dst[v] = make_uint4(frag[4 * v], frag[4 * v + 1], frag[4 * v + 2], frag[4 * v + 3]);
    }

    __threadfence();
#if __CUDA_ARCH__ >= 900
    cudaTriggerProgrammaticLaunchCompletion();
#endif
}

// ---------------- helpers ----------------
__device__ __forceinline__ u32 pack_bf16x2(float lo, float hi) {
    u32 d;
    asm("cvt.rn.bf16x2.f32 %0, %1, %2;" : "=r"(d) : "f"(hi), "f"(lo));
    return d;
}
__device__ __forceinline__ void mma_bf16(float c[4], const u32 a[4], const u32 b[2]) {
    asm volatile(
        "mma.sync.aligned.m16n8k16.row.col.f32.bf16.bf16.f32 "
        "{%0,%1,%2,%3}, {%4,%5,%6,%7}, {%8,%9}, {%0,%1,%2,%3};"
        : "+f"(c[0]), "+f"(c[1]), "+f"(c[2]), "+f"(c[3])
        : "r"(a[0]), "r"(a[1]), "r"(a[2]), "r"(a[3]), "r"(b[0]), "r"(b[1]));
}
__device__ __forceinline__ void ldsm_x4(u32 r[4], u32 saddr) {
    asm volatile("ldmatrix.sync.aligned.m8n8.x4.shared.b16 {%0,%1,%2,%3}, [%4];"
                 : "=r"(r[0]), "=r"(r[1]), "=r"(r[2]), "=r"(r[3]) : "r"(saddr));
}

// ---------------------------------------------------------------------------
// Main kernel: 1 patch/thread; warp does 32 patches = 2 m16 MMA tiles.
// y = U psi0 via bf16-split mma; expvals via a second (Z-matrix) mma.
// ---------------------------------------------------------------------------
__global__ void __launch_bounds__(256) quanv_kernel(
    const float* __restrict__ x, float* __restrict__ out, int npatch)
{
    // staging: 8 warps x 32 patch slots x 80B (Ph[16 bf16] @0, Pl @32, pad)
    __shared__ __align__(16) unsigned char stage[8 * 32 * 80];

    const int tid  = threadIdx.x;
    const int lane = tid & 31;
    const int wrp  = tid >> 5;
    const int g    = lane >> 2;   // mma groupID
    const int t    = lane & 3;    // mma threadID-in-group

    const int warpbase = blockIdx.x * 256 + wrp * 32;
    const int p  = warpbase + lane;
    const int pc = (p < npatch) ? p : (npatch - 1);

    // ---- patch -> pixels ----
    const int b  = pc / 196;
    const int q  = pc - b * 196;
    const int r  = q / 14;
    const int cc = q - r * 14;
    const float* base = x + b * 784 + r * 56 + cc * 2;
    const float2 v01 = *(const float2*)(base);
    const float2 v23 = *(const float2*)(base + 28);

    // ---- psi0 (real, 16) ----
    const float HPI = 1.5707963267948966f;
    float a0, b0, a1, b1, a2, b2, a3, b3;
    __sincosf(v01.x * HPI, &b0, &a0);
    __sincosf(v01.y * HPI, &b1, &a1);
    __sincosf(v23.x * HPI, &b2, &a2);
    __sincosf(v23.y * HPI, &b3, &a3);
    const float q01[4] = { a0 * a1, a0 * b1, b0 * a1, b0 * b1 };
    const float q23[4] = { a2 * a3, a2 * b3, b2 * a3, b2 * b3 };

    float v[DIM];
#pragma unroll
    for (int a = 0; a < 4; a++)
#pragma unroll
        for (int c = 0; c < 4; c++) v[4 * a + c] = q01[a] * q23[c];

    // ---- bf16 split + pack ----
    u32 ph[8], pl[8];
#pragma unroll
    for (int m = 0; m < 8; m++) {
        const float lo = v[2 * m], hi = v[2 * m + 1];
        const u32 p2 = pack_bf16x2(lo, hi);
        const float flo = __uint_as_float(p2 << 16);
        const float fhi = __uint_as_float(p2 & 0xffff0000u);
        ph[m] = p2;
        pl[m] = pack_bf16x2(lo - flo, hi - fhi);
    }

    // ---- stage to SMEM ----
    unsigned char* const ws = stage + wrp * (32 * 80);
    {
        uint4* slot = (uint4*)(ws + lane * 80);
        slot[0] = make_uint4(ph[0], ph[1], ph[2], ph[3]);
        slot[1] = make_uint4(ph[4], ph[5], ph[6], ph[7]);
        slot[2] = make_uint4(pl[0], pl[1], pl[2], pl[3]);
        slot[3] = make_uint4(pl[4], pl[5], pl[6], pl[7]);
    }
    __syncwarp();

    // ---- Z-matrix B fragment (compile-time-ish, pure ALU) ----
    u32 Bz[2];
    if (g < 4) {
        const u32 s0 = ((2 * t)     >> (3 - g)) & 1 ? 0xBF80u : 0x3F80u;
        const u32 s1 = ((2 * t + 1) >> (3 - g)) & 1 ? 0xBF80u : 0x3F80u;
        const u32 s2 = ((2 * t + 8) >> (3 - g)) & 1 ? 0xBF80u : 0x3F80u;
        const u32 s3 = ((2 * t + 9) >> (3 - g)) & 1 ? 0xBF80u : 0x3F80u;
        Bz[0] = s0 | (s1 << 16);
        Bz[1] = s2 | (s3 << 16);
    } else { Bz[0] = 0u; Bz[1] = 0u; }

    // ---- wait for build_U (PDL), then load U B-fragments ----
#if __CUDA_ARCH__ >= 900
    cudaGridDependencySynchronize();
#endif
    u32 Bhr[2][2], Bhi[2][2], Blr[2][2], Bli[2][2];
    {
        const uint4* bfv = ((const uint4*)g_Bfrag) + lane * 4;
        const uint4 vhr = bfv[0], vhi = bfv[1], vlr = bfv[2], vli = bfv[3];
        Bhr[0][0] = vhr.x; Bhr[0][1] = vhr.y; Bhr[1][0] = vhr.z; Bhr[1][1] = vhr.w;
        Bhi[0][0] = vhi.x; Bhi[0][1] = vhi.y; Bhi[1][0] = vhi.z; Bhi[1][1] = vhi.w;
        Blr[0][0] = vlr.x; Blr[0][1] = vlr.y; Blr[1][0] = vlr.z; Blr[1][1] = vlr.w;
        Bli[0][0] = vli.x; Bli[0][1] = vli.y; Bli[1][0] = vli.z; Bli[1][1] = vli.w;
    }

    // ldmatrix source address for this lane (within a tile):
    // row = lane&15, k-half = lane>>4
    const u32 wsa   = (u32)__cvta_generic_to_shared(ws);
    const u32 rowa  = wsa + (u32)((lane & 15) * 80 + (lane >> 4) * 16);

#pragma unroll
    for (int T = 0; T < 2; T++) {
        // ---- A fragments via ldmatrix ----
        u32 Aph[4], Apl[4];
        ldsm_x4(Aph, rowa + T * 16 * 80);
        ldsm_x4(Apl, rowa + T * 16 * 80 + 32);

        // ---- main MMAs: y = U psi0 (bf16-split, fp32 accum) ----
        float Cr[2][4], Ci[2][4];
#pragma unroll
        for (int nt = 0; nt < 2; nt++)
#pragma unroll
            for (int k = 0; k < 4; k++) { Cr[nt][k] = 0.0f; Ci[nt][k] = 0.0f; }

#pragma unroll
        for (int nt = 0; nt < 2; nt++) {
            mma_bf16(Cr[nt], Aph, Bhr[nt]);
            mma_bf16(Cr[nt], Apl, Bhr[nt]);
            mma_bf16(Cr[nt], Aph, Blr[nt]);
            mma_bf16(Ci[nt], Aph, Bhi[nt]);
            mma_bf16(Ci[nt], Apl, Bhi[nt]);
            mma_bf16(Ci[nt], Aph, Bli[nt]);
        }

        // ---- probs, split to bf16, Z-MMA ----
        // C layout: nt gives k-half; c0,c1 = (row g, k 2t,2t+1), c2,c3 = (row g+8, same k)
        float pr[2][4];
#pragma unroll
        for (int nt = 0; nt < 2; nt++)
#pragma unroll
            for (int k = 0; k < 4; k++)
                pr[nt][k] = fmaf(Cr[nt][k], Cr[nt][k], Ci[nt][k] * Ci[nt][k]);

        u32 Ah[4], Al[4];
        // a0=(g, k2t..): nt0 c0,c1 | a1=(g+8): nt0 c2,c3 | a2: nt1 c0,c1 | a3: nt1 c2,c3
#pragma unroll
        for (int j = 0; j < 4; j++) {
            const int nt = j >> 1, hi8 = j & 1;
            const float plo = pr[nt][2 * hi8], phi = pr[nt][2 * hi8 + 1];
            const u32 p2 = pack_bf16x2(plo, phi);
            const float flo = __uint_as_float(p2 << 16);
            const float fhi = __uint_as_float(p2 & 0xffff0000u);
            Ah[j] = p2;
            Al[j] = pack_bf16x2(plo - flo, phi - fhi);
        }

        float E[4] = {0.0f, 0.0f, 0.0f, 0.0f};
        mma_bf16(E, Ah, Bz);
        mma_bf16(E, Al, Bz);

        // lane (g, t<2) holds expval cols 2t,2t+1 for patch rows g (E0,E1) and g+8 (E2,E3)
        if (t < 2) {
            const int p0s = warpbase + T * 16 + g;
            const int p1s = p0s + 8;
            if (p0s < npatch) *(float2*)(out + 4 * p0s + 2 * t) = make_float2(E[0], E[1]);
            if (p1s < npatch) *(float2*)(out + 4 * p1s + 2 * t) = make_float2(E[2], E[3]);
        }
    }
}

extern "C" void kernel_launch(void* const* d_in, const int* in_sizes, int n_in,
                              void* d_out, int out_size) {
    const float* x      = (const float*)d_in[0];
    const float* params = (const float*)d_in[1];
    float* out = (float*)d_out;

    const int bsz    = in_sizes[0] / 784;
    const int npatch = bsz * 196;

    build_U_kernel<<<1, 32>>>(params);

    const int threads = 256;
    const int blocks  = (npatch + threads - 1) / threads;

    // PDL: quanv may launch while build_U still runs; quanv's front phase
    // overlaps build_U, and cudaGridDependencySynchronize() gates U loads.
    cudaLaunchConfig_t cfg = {};
    cfg.gridDim  = dim3(blocks, 1, 1);
    cfg.blockDim = dim3(threads, 1, 1);
    cfg.dynamicSmemBytes = 0;
    cfg.stream = 0;
    cudaLaunchAttribute attr[1];
    attr[0].id = cudaLaunchAttributeProgrammaticStreamSerialization;
    attr[0].val.programmaticStreamSerializationAllowed = 1;
    cfg.attrs = attr;
    cfg.numAttrs = 1;
    cudaError_t e = cudaLaunchKernelEx(&cfg, quanv_kernel, x, out, npatch);
    if (e != cudaSuccess) {
        // fallback: plain launch (still correct, just no overlap)
        quanv_kernel<<<blocks, threads>>>(x, out, npatch);
    }
}

// round 5
// speedup vs baseline: 1.6840x; 1.0992x over previous
#include <cuda_runtime.h>
#include <cuda_bf16.h>

#define NQ 4
#define DIM 16
#define NPARAMS 36

typedef unsigned int u32;
typedef unsigned long long u64;

// bf16-split of the 16x16 unitary, row-major [k][j]
__device__ __nv_bfloat16 g_Uh_r[DIM][DIM];
__device__ __nv_bfloat16 g_Ul_r[DIM][DIM];
__device__ __nv_bfloat16 g_Uh_i[DIM][DIM];
__device__ __nv_bfloat16 g_Ul_i[DIM][DIM];

// Per-lane pre-packed B fragments: [lane][16] u32
__device__ u32 g_Bfrag[32][16];

// ---------------------------------------------------------------------------
// Build U(params): threads 0..15 each own one COLUMN of U; then repack.
// ---------------------------------------------------------------------------
__global__ void build_U_kernel(const float* __restrict__ params) {
    const int c = threadIdx.x;

    if (c < DIM) {
        float P[NPARAMS];
#pragma unroll
        for (int i = 0; i < NPARAMS; i++) P[i] = params[i];

        float ur[DIM], ui[DIM];
#pragma unroll
        for (int j = 0; j < DIM; j++) { ur[j] = (j == c) ? 1.0f : 0.0f; ui[j] = 0.0f; }

        int off = 0;
#pragma unroll
        for (int layer = 0; layer < 3; layer++) {
#pragma unroll
            for (int w = 0; w < NQ; w++) {
                const int bit = 1 << (NQ - 1 - w);
                // RY
                {
                    float s, co; __sincosf(0.5f * P[off], &s, &co); off++;
#pragma unroll
                    for (int r = 0; r < DIM; r++) {
                        if (r & bit) continue;
                        const int r1 = r | bit;
                        float v0r = ur[r], v0i = ui[r], v1r = ur[r1], v1i = ui[r1];
                        ur[r]  = co * v0r - s * v1r;   ui[r]  = co * v0i - s * v1i;
                        ur[r1] = s * v0r + co * v1r;   ui[r1] = s * v0i + co * v1i;
                    }
                }
                // RZ
                {
                    float s, co; __sincosf(0.5f * P[off], &s, &co); off++;
#pragma unroll
                    for (int r = 0; r < DIM; r++) {
                        float vr = ur[r], vi = ui[r];
                        if (r & bit) { ur[r] = co * vr - s * vi; ui[r] = co * vi + s * vr; }
                        else         { ur[r] = co * vr + s * vi; ui[r] = co * vi - s * vr; }
                    }
                }
                // RY
                {
                    float s, co; __sincosf(0.5f * P[off], &s, &co); off++;
#pragma unroll
                    for (int r = 0; r < DIM; r++) {
                        if (r & bit) continue;
                        const int r1 = r | bit;
                        float v0r = ur[r], v0i = ui[r], v1r = ur[r1], v1i = ui[r1];
                        ur[r]  = co * v0r - s * v1r;   ui[r]  = co * v0i - s * v1i;
                        ur[r1] = s * v0r + co * v1r;   ui[r1] = s * v0i + co * v1i;
                    }
                }
            }
            // CNOT ring = row swaps
#pragma unroll
            for (int g = 0; g < NQ; g++) {
                const int cb = 1 << (NQ - 1 - g);
                const int tb = 1 << (NQ - 1 - ((g + 1) & 3));
#pragma unroll
                for (int r = 0; r < DIM; r++) {
                    if ((r & cb) && !(r & tb)) {
                        const int r1 = r | tb;
                        float t;
                        t = ur[r]; ur[r] = ur[r1]; ur[r1] = t;
                        t = ui[r]; ui[r] = ui[r1]; ui[r1] = t;
                    }
                }
            }
        }

#pragma unroll
        for (int k = 0; k < DIM; k++) {
            __nv_bfloat16 h;
            h = __float2bfloat16(ur[k]);
            g_Uh_r[k][c] = h;
            g_Ul_r[k][c] = __float2bfloat16(ur[k] - __bfloat162float(h));
            h = __float2bfloat16(ui[k]);
            g_Uh_i[k][c] = h;
            g_Ul_i[k][c] = __float2bfloat16(ui[k] - __bfloat162float(h));
        }
    }

    __syncthreads();

    // Pack per-lane B fragments (lane = g*4 + t)
    {
        const int lane = threadIdx.x;
        const int g = lane >> 2, t = lane & 3;
        u32 frag[16];
#pragma unroll
        for (int nt = 0; nt < 2; nt++) {
            const int kk = 8 * nt + g;
            frag[0  + 2 * nt] = *(const u32*)&g_Uh_r[kk][2 * t];
            frag[1  + 2 * nt] = *(const u32*)&g_Uh_r[kk][2 * t + 8];
            frag[4  + 2 * nt] = *(const u32*)&g_Uh_i[kk][2 * t];
            frag[5  + 2 * nt] = *(const u32*)&g_Uh_i[kk][2 * t + 8];
            frag[8  + 2 * nt] = *(const u32*)&g_Ul_r[kk][2 * t];
            frag[9  + 2 * nt] = *(const u32*)&g_Ul_r[kk][2 * t + 8];
            frag[12 + 2 * nt] = *(const u32*)&g_Ul_i[kk][2 * t];
            frag[13 + 2 * nt] = *(const u32*)&g_Ul_i[kk][2 * t + 8];
        }
        uint4* dst = (uint4*)g_Bfrag[lane];
#pragma unroll
        for (int v = 0; v < 4; v++)
            dst[v] = make_uint4(frag[4 * v], frag[4 * v + 1], frag[4 * v + 2], frag[4 * v + 3]);
    }
}

// ---------------- helpers ----------------
__device__ __forceinline__ u32 pack_bf16x2(float lo, float hi) {
    u32 d;
    asm("cvt.rn.bf16x2.f32 %0, %1, %2;" : "=r"(d) : "f"(hi), "f"(lo));
    return d;
}
__device__ __forceinline__ u64 pack2(float lo, float hi) {
    u64 d;
    asm("mov.b64 %0, {%1, %2};" : "=l"(d) : "f"(lo), "f"(hi));
    return d;
}
__device__ __forceinline__ void unpack2(u64 v, float& lo, float& hi) {
    asm("mov.b64 {%0, %1}, %2;" : "=f"(lo), "=f"(hi) : "l"(v));
}
__device__ __forceinline__ u64 mul2(u64 a, u64 b) {
    u64 d;
    asm("mul.rn.f32x2 %0, %1, %2;" : "=l"(d) : "l"(a), "l"(b));
    return d;
}
__device__ __forceinline__ u64 fma2(u64 a, u64 b, u64 c) {
    u64 d;
    asm("fma.rn.f32x2 %0, %1, %2, %3;" : "=l"(d) : "l"(a), "l"(b), "l"(c));
    return d;
}
__device__ __forceinline__ void mma_bf16(float c[4], const u32 a[4], const u32 b[2]) {
    asm volatile(
        "mma.sync.aligned.m16n8k16.row.col.f32.bf16.bf16.f32 "
        "{%0,%1,%2,%3}, {%4,%5,%6,%7}, {%8,%9}, {%0,%1,%2,%3};"
        : "+f"(c[0]), "+f"(c[1]), "+f"(c[2]), "+f"(c[3])
        : "r"(a[0]), "r"(a[1]), "r"(a[2]), "r"(a[3]), "r"(b[0]), "r"(b[1]));
}
__device__ __forceinline__ void ldsm_x4(u32 r[4], u32 saddr) {
    asm volatile("ldmatrix.sync.aligned.m8n8.x4.shared.b16 {%0,%1,%2,%3}, [%4];"
                 : "=r"(r[0]), "=r"(r[1]), "=r"(r[2]), "=r"(r[3]) : "r"(saddr));
}

// ---------------------------------------------------------------------------
// Main kernel: 2 patches/thread; warp does 64 patches = 4 m16 MMA tiles.
// ---------------------------------------------------------------------------
__global__ void __launch_bounds__(256) quanv_kernel(
    const float* __restrict__ x, float* __restrict__ out, int npatch)
{
    // staging: 8 warps x 64 patch slots x 80B (Ph[16 bf16] @0, Pl @32, pad)
    __shared__ __align__(16) unsigned char stage[8 * 64 * 80];

    const int tid  = threadIdx.x;
    const int lane = tid & 31;
    const int wrp  = tid >> 5;
    const int g    = lane >> 2;
    const int t    = lane & 3;

    const int warpbase = blockIdx.x * 512 + wrp * 64;
    unsigned char* const ws = stage + wrp * (64 * 80);

    const float HPI = 1.5707963267948966f;
    const u64 NEG1 = pack2(-1.0f, -1.0f);

    // ---- front phase: two patches ----
    // compute both addresses first for MLP
    const float* basep[2];
#pragma unroll
    for (int pp = 0; pp < 2; pp++) {
        const int p  = warpbase + pp * 32 + lane;
        const int pc = (p < npatch) ? p : (npatch - 1);
        const int b  = pc / 196;
        const int q  = pc - b * 196;
        const int r  = q / 14;
        const int cc = q - r * 14;
        basep[pp] = x + b * 784 + r * 56 + cc * 2;
    }
    float2 V01[2], V23[2];
#pragma unroll
    for (int pp = 0; pp < 2; pp++) {
        V01[pp] = *(const float2*)(basep[pp]);
        V23[pp] = *(const float2*)(basep[pp] + 28);
    }

#pragma unroll
    for (int pp = 0; pp < 2; pp++) {
        float a0, b0, a1, b1, a2, b2, a3, b3;
        __sincosf(V01[pp].x * HPI, &b0, &a0);
        __sincosf(V01[pp].y * HPI, &b1, &a1);
        __sincosf(V23[pp].x * HPI, &b2, &a2);
        __sincosf(V23[pp].y * HPI, &b3, &a3);
        const float q01[4] = { a0 * a1, a0 * b1, b0 * a1, b0 * b1 };
        const float q23[4] = { a2 * a3, a2 * b3, b2 * a3, b2 * b3 };

        const u64 P23a = pack2(q23[0], q23[1]);
        const u64 P23b = pack2(q23[2], q23[3]);

        u32 ph[8], pl[8];
#pragma unroll
        for (int a = 0; a < 4; a++) {
            const u64 qd = pack2(q01[a], q01[a]);
            const u64 vA = mul2(qd, P23a);   // v[4a], v[4a+1]
            const u64 vB = mul2(qd, P23b);   // v[4a+2], v[4a+3]
#pragma unroll
            for (int h = 0; h < 2; h++) {
                const u64 vp = h ? vB : vA;
                float lo, hi; unpack2(vp, lo, hi);
                const u32 p2 = pack_bf16x2(lo, hi);
                const u64 fp = pack2(__uint_as_float(p2 << 16),
                                     __uint_as_float(p2 & 0xffff0000u));
                const u64 res = fma2(fp, NEG1, vp);   // v - bf16(v)
                float rlo, rhi; unpack2(res, rlo, rhi);
                ph[2 * a + h] = p2;
                pl[2 * a + h] = pack_bf16x2(rlo, rhi);
            }
        }

        uint4* slot = (uint4*)(ws + (pp * 32 + lane) * 80);
        slot[0] = make_uint4(ph[0], ph[1], ph[2], ph[3]);
        slot[1] = make_uint4(ph[4], ph[5], ph[6], ph[7]);
        slot[2] = make_uint4(pl[0], pl[1], pl[2], pl[3]);
        slot[3] = make_uint4(pl[4], pl[5], pl[6], pl[7]);
    }
    __syncwarp();

    // ---- Z-matrix B fragment ----
    u32 Bz[2];
    if (g < 4) {
        const u32 s0 = ((2 * t)     >> (3 - g)) & 1 ? 0xBF80u : 0x3F80u;
        const u32 s1 = ((2 * t + 1) >> (3 - g)) & 1 ? 0xBF80u : 0x3F80u;
        const u32 s2 = ((2 * t + 8) >> (3 - g)) & 1 ? 0xBF80u : 0x3F80u;
        const u32 s3 = ((2 * t + 9) >> (3 - g)) & 1 ? 0xBF80u : 0x3F80u;
        Bz[0] = s0 | (s1 << 16);
        Bz[1] = s2 | (s3 << 16);
    } else { Bz[0] = 0u; Bz[1] = 0u; }

    // ---- U B-fragments (per warp, all tiles) ----
    u32 Bhr[2][2], Bhi[2][2], Blr[2][2], Bli[2][2];
    {
        const uint4* bfv = ((const uint4*)g_Bfrag) + lane * 4;
        const uint4 vhr = bfv[0], vhi = bfv[1], vlr = bfv[2], vli = bfv[3];
        Bhr[0][0] = vhr.x; Bhr[0][1] = vhr.y; Bhr[1][0] = vhr.z; Bhr[1][1] = vhr.w;
        Bhi[0][0] = vhi.x; Bhi[0][1] = vhi.y; Bhi[1][0] = vhi.z; Bhi[1][1] = vhi.w;
        Blr[0][0] = vlr.x; Blr[0][1] = vlr.y; Blr[1][0] = vlr.z; Blr[1][1] = vlr.w;
        Bli[0][0] = vli.x; Bli[0][1] = vli.y; Bli[1][0] = vli.z; Bli[1][1] = vli.w;
    }

    const u32 wsa  = (u32)__cvta_generic_to_shared(ws);
    const u32 rowa = wsa + (u32)((lane & 15) * 80 + (lane >> 4) * 16);

#pragma unroll
    for (int T = 0; T < 4; T++) {
        u32 Aph[4], Apl[4];
        ldsm_x4(Aph, rowa + T * 16 * 80);
        ldsm_x4(Apl, rowa + T * 16 * 80 + 32);

        float Cr[2][4], Ci[2][4];
#pragma unroll
        for (int nt = 0; nt < 2; nt++)
#pragma unroll
            for (int k = 0; k < 4; k++) { Cr[nt][k] = 0.0f; Ci[nt][k] = 0.0f; }

#pragma unroll
        for (int nt = 0; nt < 2; nt++) {
            mma_bf16(Cr[nt], Aph, Bhr[nt]);
            mma_bf16(Cr[nt], Apl, Bhr[nt]);
            mma_bf16(Cr[nt], Aph, Blr[nt]);
            mma_bf16(Ci[nt], Aph, Bhi[nt]);
            mma_bf16(Ci[nt], Apl, Bhi[nt]);
            mma_bf16(Ci[nt], Aph, Bli[nt]);
        }

        float pr[2][4];
#pragma unroll
        for (int nt = 0; nt < 2; nt++)
#pragma unroll
            for (int k = 0; k < 4; k++)
                pr[nt][k] = fmaf(Cr[nt][k], Cr[nt][k], Ci[nt][k] * Ci[nt][k]);

        u32 Ah[4], Al[4];
#pragma unroll
        for (int j = 0; j < 4; j++) {
            const int nt = j >> 1, hi8 = j & 1;
            const float plo = pr[nt][2 * hi8], phi = pr[nt][2 * hi8 + 1];
            const u32 p2 = pack_bf16x2(plo, phi);
            const u64 fp = pack2(__uint_as_float(p2 << 16),
                                 __uint_as_float(p2 & 0xffff0000u));
            const u64 vp = pack2(plo, phi);
            const u64 res = fma2(fp, NEG1, vp);
            float rlo, rhi; unpack2(res, rlo, rhi);
            Ah[j] = p2;
            Al[j] = pack_bf16x2(rlo, rhi);
        }

        float E[4] = {0.0f, 0.0f, 0.0f, 0.0f};
        mma_bf16(E, Ah, Bz);
        mma_bf16(E, Al, Bz);

        if (t < 2) {
            const int p0s = warpbase + T * 16 + g;
            const int p1s = p0s + 8;
            if (p0s < npatch) *(float2*)(out + 4 * p0s + 2 * t) = make_float2(E[0], E[1]);
            if (p1s < npatch) *(float2*)(out + 4 * p1s + 2 * t) = make_float2(E[2], E[3]);
        }
    }
}

extern "C" void kernel_launch(void* const* d_in, const int* in_sizes, int n_in,
                              void* d_out, int out_size) {
    const float* x      = (const float*)d_in[0];
    const float* params = (const float*)d_in[1];
    float* out = (float*)d_out;

    const int bsz    = in_sizes[0] / 784;
    const int npatch = bsz * 196;

    build_U_kernel<<<1, 32>>>(params);

    const int blocks = (npatch + 511) / 512;
    quanv_kernel<<<blocks, 256>>>(x, out, npatch);
}